// round 3
// baseline (speedup 1.0000x reference)
#include <cuda_runtime.h>
#include <cuda_bf16.h>
#include <math.h>

// ---------------------------------------------------------------------------
// EncoderBlock: fp32 baseline with FFMA2 (fma.rn.f32x2) GEMMs + flash attention
//   x -> LN1 -> QKV gemm -> attention -> proj gemm (+x residual) -> LN2
//     -> fc1 gemm (+GELU) -> fc2 gemm (+ff_in residual) -> LN3 -> out
// Shapes: B=16, N=1024, DIM=768, HEADS=12, HEAD_DIM=64, HIDDEN=3072
// ---------------------------------------------------------------------------

#define TOKENS   16384        // B*N
#define DIM      768
#define HEADS    12
#define HEAD_DIM 64
#define HIDDEN   3072
#define QKV_N    2304         // 3*DIM
#define LN_EPS   1e-5f

// ----------------------------- scratch (device globals; no cudaMalloc) -----
__device__ __align__(256) float g_xn1 [TOKENS * DIM];     // LN1(x)
__device__ __align__(256) float g_qkv [TOKENS * QKV_N];   // qkv projections
__device__ __align__(256) float g_ctx [TOKENS * DIM];     // attention context
__device__ __align__(256) float g_xa  [TOKENS * DIM];     // x + attn_out
__device__ __align__(256) float g_ffin[TOKENS * DIM];     // LN2(x_after_attn)
__device__ __align__(256) float g_hid [TOKENS * HIDDEN];  // gelu(fc1)
__device__ __align__(256) float g_xmlp[TOKENS * DIM];     // ff_in + ff_out

// ----------------------------- f32x2 helpers (sm_103a packed fp32) ---------
__device__ __forceinline__ unsigned long long frep2(float a) {
    unsigned long long r;
    unsigned ia = __float_as_uint(a);
    asm("mov.b64 %0, {%1,%2};" : "=l"(r) : "r"(ia), "r"(ia));
    return r;
}
__device__ __forceinline__ void ffma2(unsigned long long& d,
                                      unsigned long long a,
                                      unsigned long long b) {
    asm("fma.rn.f32x2 %0, %1, %2, %0;" : "+l"(d) : "l"(a), "l"(b));
}
__device__ __forceinline__ float2 funpack2(unsigned long long v) {
    unsigned lo, hi;
    asm("mov.b64 {%0,%1}, %2;" : "=r"(lo), "=r"(hi) : "l"(v));
    return make_float2(__uint_as_float(lo), __uint_as_float(hi));
}

__device__ __forceinline__ float gelu_exact(float v) {
    return 0.5f * v * (1.0f + erff(v * 0.70710678118654752f));
}

// ----------------------------- LayerNorm over last dim (768) ---------------
// one block (256 threads) per row; each thread owns 3 strided elements
__global__ void eb_ln_kernel(const float* __restrict__ x,
                             const float* __restrict__ g,
                             const float* __restrict__ b,
                             float* __restrict__ y) {
    int row = blockIdx.x;
    const float* xr = x + (size_t)row * DIM;
    int t = threadIdx.x;
    float v0 = xr[t], v1 = xr[t + 256], v2 = xr[t + 512];
    float s = v0 + v1 + v2;
    float q = v0 * v0 + v1 * v1 + v2 * v2;
    #pragma unroll
    for (int m = 16; m > 0; m >>= 1) {
        s += __shfl_xor_sync(0xffffffffu, s, m);
        q += __shfl_xor_sync(0xffffffffu, q, m);
    }
    __shared__ float ss[8], sq[8];
    __shared__ float mean_s, rstd_s;
    int w = t >> 5, lane = t & 31;
    if (lane == 0) { ss[w] = s; sq[w] = q; }
    __syncthreads();
    if (t == 0) {
        float S = 0.f, Q = 0.f;
        #pragma unroll
        for (int i = 0; i < 8; i++) { S += ss[i]; Q += sq[i]; }
        float mean = S * (1.0f / DIM);
        float var  = Q * (1.0f / DIM) - mean * mean;
        mean_s = mean;
        rstd_s = rsqrtf(var + LN_EPS);
    }
    __syncthreads();
    float mean = mean_s, rstd = rstd_s;
    float* yr = y + (size_t)row * DIM;
    yr[t]       = (v0 - mean) * rstd * g[t]       + b[t];
    yr[t + 256] = (v1 - mean) * rstd * g[t + 256] + b[t + 256];
    yr[t + 512] = (v2 - mean) * rstd * g[t + 512] + b[t + 512];
}

// ----------------------------- tiled fp32 GEMM with f32x2 inner loop -------
// C[M,N] = epilogue(A[M,K] @ W[K,N] + bias [, residual R])
// EPI: 0 = bias, 1 = bias + residual add, 2 = bias + exact GELU
// Tile: BM=128, BN=128, BK=16, 256 threads, 8x8 outputs/thread.
// All problem dims here are multiples of the tile dims (no bounds checks).
#define GBM 128
#define GBN 128
#define GBK 16

template <int EPI>
__global__ __launch_bounds__(256, 2)
void eb_gemm_kernel(const float* __restrict__ A,
                    const float* __restrict__ W,
                    const float* __restrict__ bias,
                    const float* __restrict__ R,
                    float* __restrict__ C,
                    int M, int K, int N) {
    __shared__ __align__(16) float As[GBK][GBM + 4];  // [k][m] transposed
    __shared__ __align__(16) float Bs[GBK][GBN + 4];  // [k][n]
    int tid = threadIdx.x;
    int tx = tid & 15;         // 16 col-groups of 8
    int ty = tid >> 4;         // 16 row-groups of 8
    int n0 = blockIdx.x * GBN;
    int m0 = blockIdx.y * GBM;

    unsigned long long acc[8][4];   // [row][col-pair], f32x2 packed
    #pragma unroll
    for (int i = 0; i < 8; i++)
        #pragma unroll
        for (int j = 0; j < 4; j++) acc[i][j] = 0ull;

    int ar0 = tid >> 2;            // 0..63  (A rows, two passes)
    int ac  = (tid & 3) * 4;       // 0,4,8,12 (A k-cols, float4)
    int br0 = tid >> 5;            // 0..7   (B k-rows, two passes)
    int bc  = (tid & 31) * 4;      // 0..124 (B n-cols, float4)

    for (int k0 = 0; k0 < K; k0 += GBK) {
        #pragma unroll
        for (int i = 0; i < 2; i++) {
            int r = ar0 + i * 64;
            float4 v = *(const float4*)&A[(size_t)(m0 + r) * K + k0 + ac];
            As[ac + 0][r] = v.x; As[ac + 1][r] = v.y;
            As[ac + 2][r] = v.z; As[ac + 3][r] = v.w;
        }
        #pragma unroll
        for (int i = 0; i < 2; i++) {
            int r = br0 + i * 8;
            float4 v = *(const float4*)&W[(size_t)(k0 + r) * N + n0 + bc];
            *(float4*)&Bs[r][bc] = v;
        }
        __syncthreads();
        #pragma unroll
        for (int kk = 0; kk < GBK; kk++) {
            float4 aA = *(const float4*)&As[kk][ty * 8];
            float4 aB = *(const float4*)&As[kk][ty * 8 + 4];
            ulonglong2 u0 = *(const ulonglong2*)&Bs[kk][tx * 8];
            ulonglong2 u1 = *(const ulonglong2*)&Bs[kk][tx * 8 + 4];
            unsigned long long b0 = u0.x, b1 = u0.y, b2 = u1.x, b3 = u1.y;
            float a[8] = {aA.x, aA.y, aA.z, aA.w, aB.x, aB.y, aB.z, aB.w};
            #pragma unroll
            for (int r = 0; r < 8; r++) {
                unsigned long long ar = frep2(a[r]);
                ffma2(acc[r][0], ar, b0);
                ffma2(acc[r][1], ar, b1);
                ffma2(acc[r][2], ar, b2);
                ffma2(acc[r][3], ar, b3);
            }
        }
        __syncthreads();
    }

    #pragma unroll
    for (int r = 0; r < 8; r++) {
        int grow = m0 + ty * 8 + r;
        #pragma unroll
        for (int j = 0; j < 4; j++) {
            int gcol = n0 + tx * 8 + j * 2;
            float2 v = funpack2(acc[r][j]);
            v.x += bias[gcol];
            v.y += bias[gcol + 1];
            if (EPI == 1) {
                v.x += R[(size_t)grow * N + gcol];
                v.y += R[(size_t)grow * N + gcol + 1];
            }
            if (EPI == 2) {
                v.x = gelu_exact(v.x);
                v.y = gelu_exact(v.y);
            }
            *(float2*)&C[(size_t)grow * N + gcol] = v;
        }
    }
}

// ----------------------------- flash attention --------------------------------
// grid (16 q-tiles, 192 bh); 128 threads. q-tile = 64 rows; k-tiles of 64.
// smem: Qt[d][r] (scaled), KP[..] (K transposed [d][c], reused as P [r][c]),
//       Vs[c][d]. Online softmax, fp32 accumulation.
#define APAD 68
#define ATTN_SMEM (3 * 64 * APAD * 4)

__global__ __launch_bounds__(128, 4)
void eb_attn_kernel(const float* __restrict__ qkv, float* __restrict__ ctx) {
    extern __shared__ __align__(16) float smem[];
    float (*Qt)[APAD] = (float(*)[APAD])(smem);                // [d][r]
    float (*KP)[APAD] = (float(*)[APAD])(smem + 64 * APAD);    // K:[d][c] / P:[r][c]
    float (*Vs)[APAD] = (float(*)[APAD])(smem + 2 * 64 * APAD);// [c][d]

    int tid = threadIdx.x;
    int tx = tid & 15;       // 16 groups of 4 cols
    int ty = tid >> 4;       // 8 groups of 8 rows
    int bh = blockIdx.y;
    int b = bh / HEADS, h = bh % HEADS;
    int q0 = blockIdx.x * 64;
    size_t rowbase = (size_t)b * 1024;
    const int LD = QKV_N;
    int qoff = h * HEAD_DIM;
    int koff = DIM + h * HEAD_DIM;
    int voff = 2 * DIM + h * HEAD_DIM;

    // load Q tile, transposed + pre-scaled by 1/sqrt(Dh)
    {
        int r = tid >> 1;
        int cb = (tid & 1) * 32;
        #pragma unroll
        for (int i = 0; i < 8; i++) {
            int c = cb + i * 4;
            float4 v = *(const float4*)&qkv[(rowbase + q0 + r) * LD + qoff + c];
            Qt[c + 0][r] = v.x * 0.125f; Qt[c + 1][r] = v.y * 0.125f;
            Qt[c + 2][r] = v.z * 0.125f; Qt[c + 3][r] = v.w * 0.125f;
        }
    }

    float acc[8][4];
    float m_run[8], l_run[8];
    #pragma unroll
    for (int i = 0; i < 8; i++) {
        m_run[i] = -3.0e38f;
        l_run[i] = 0.f;
        #pragma unroll
        for (int j = 0; j < 4; j++) acc[i][j] = 0.f;
    }

    for (int kt = 0; kt < 16; kt++) {
        int kr0 = kt * 64;
        __syncthreads();   // previous PV done reading KP/Vs (and Q load done, iter 0)
        {
            int r = tid >> 1;
            int cb = (tid & 1) * 32;
            #pragma unroll
            for (int i = 0; i < 8; i++) {
                int c = cb + i * 4;
                float4 v = *(const float4*)&qkv[(rowbase + kr0 + r) * LD + koff + c];
                KP[c + 0][r] = v.x; KP[c + 1][r] = v.y;
                KP[c + 2][r] = v.z; KP[c + 3][r] = v.w;
                float4 w = *(const float4*)&qkv[(rowbase + kr0 + r) * LD + voff + c];
                *(float4*)&Vs[r][c] = w;
            }
        }
        __syncthreads();

        // S tile: s[i][j] = sum_d Qt[d][row] * K[d][col]
        float s[8][4];
        #pragma unroll
        for (int i = 0; i < 8; i++)
            #pragma unroll
            for (int j = 0; j < 4; j++) s[i][j] = 0.f;
        #pragma unroll 4
        for (int d = 0; d < 64; d++) {
            float4 aA = *(const float4*)&Qt[d][ty * 8];
            float4 aB = *(const float4*)&Qt[d][ty * 8 + 4];
            float4 bb = *(const float4*)&KP[d][tx * 4];
            float a[8] = {aA.x, aA.y, aA.z, aA.w, aB.x, aB.y, aB.z, aB.w};
            #pragma unroll
            for (int i = 0; i < 8; i++) {
                s[i][0] = fmaf(a[i], bb.x, s[i][0]);
                s[i][1] = fmaf(a[i], bb.y, s[i][1]);
                s[i][2] = fmaf(a[i], bb.z, s[i][2]);
                s[i][3] = fmaf(a[i], bb.w, s[i][3]);
            }
        }
        __syncthreads();   // all threads done reading KP as K

        // online softmax update; write P into KP as [row][col]
        #pragma unroll
        for (int i = 0; i < 8; i++) {
            float tm = fmaxf(fmaxf(s[i][0], s[i][1]), fmaxf(s[i][2], s[i][3]));
            tm = fmaxf(tm, __shfl_xor_sync(0xffffffffu, tm, 1));
            tm = fmaxf(tm, __shfl_xor_sync(0xffffffffu, tm, 2));
            tm = fmaxf(tm, __shfl_xor_sync(0xffffffffu, tm, 4));
            tm = fmaxf(tm, __shfl_xor_sync(0xffffffffu, tm, 8));
            float mn = fmaxf(m_run[i], tm);
            float sc = __expf(m_run[i] - mn);
            float ps = 0.f;
            #pragma unroll
            for (int j = 0; j < 4; j++) {
                float p = __expf(s[i][j] - mn);
                s[i][j] = p;
                ps += p;
            }
            ps += __shfl_xor_sync(0xffffffffu, ps, 1);
            ps += __shfl_xor_sync(0xffffffffu, ps, 2);
            ps += __shfl_xor_sync(0xffffffffu, ps, 4);
            ps += __shfl_xor_sync(0xffffffffu, ps, 8);
            l_run[i] = l_run[i] * sc + ps;
            m_run[i] = mn;
            #pragma unroll
            for (int j = 0; j < 4; j++) acc[i][j] *= sc;
            *(float4*)&KP[ty * 8 + i][tx * 4] =
                make_float4(s[i][0], s[i][1], s[i][2], s[i][3]);
        }
        __syncthreads();

        // PV: acc[i][j] += sum_c P[row][c] * V[c][dcol]
        #pragma unroll 4
        for (int c = 0; c < 64; c++) {
            float4 bb = *(const float4*)&Vs[c][tx * 4];
            #pragma unroll
            for (int i = 0; i < 8; i++) {
                float p = KP[ty * 8 + i][c];
                acc[i][0] = fmaf(p, bb.x, acc[i][0]);
                acc[i][1] = fmaf(p, bb.y, acc[i][1]);
                acc[i][2] = fmaf(p, bb.z, acc[i][2]);
                acc[i][3] = fmaf(p, bb.w, acc[i][3]);
            }
        }
    }

    #pragma unroll
    for (int i = 0; i < 8; i++) {
        float inv = 1.0f / l_run[i];
        float4 o = make_float4(acc[i][0] * inv, acc[i][1] * inv,
                               acc[i][2] * inv, acc[i][3] * inv);
        *(float4*)&ctx[(rowbase + q0 + ty * 8 + i) * DIM + h * HEAD_DIM + tx * 4] = o;
    }
}

// ----------------------------- launch ---------------------------------------
extern "C" void kernel_launch(void* const* d_in, const int* in_sizes, int n_in,
                              void* d_out, int out_size) {
    const float* x      = (const float*)d_in[0];
    const float* ln1_g  = (const float*)d_in[1];
    const float* ln1_b  = (const float*)d_in[2];
    const float* qkv_w  = (const float*)d_in[3];
    const float* qkv_b  = (const float*)d_in[4];
    const float* proj_w = (const float*)d_in[5];
    const float* proj_b = (const float*)d_in[6];
    const float* ln2_g  = (const float*)d_in[7];
    const float* ln2_b  = (const float*)d_in[8];
    const float* fc1_w  = (const float*)d_in[9];
    const float* fc1_b  = (const float*)d_in[10];
    const float* fc2_w  = (const float*)d_in[11];
    const float* fc2_b  = (const float*)d_in[12];
    const float* ln3_g  = (const float*)d_in[13];
    const float* ln3_b  = (const float*)d_in[14];
    float* out = (float*)d_out;

    void *p_xn1, *p_qkv, *p_ctx, *p_xa, *p_ffin, *p_hid, *p_xmlp;
    cudaGetSymbolAddress(&p_xn1,  g_xn1);
    cudaGetSymbolAddress(&p_qkv,  g_qkv);
    cudaGetSymbolAddress(&p_ctx,  g_ctx);
    cudaGetSymbolAddress(&p_xa,   g_xa);
    cudaGetSymbolAddress(&p_ffin, g_ffin);
    cudaGetSymbolAddress(&p_hid,  g_hid);
    cudaGetSymbolAddress(&p_xmlp, g_xmlp);

    cudaFuncSetAttribute(eb_attn_kernel,
                         cudaFuncAttributeMaxDynamicSharedMemorySize, ATTN_SMEM);

    float* xn1  = (float*)p_xn1;
    float* qkv  = (float*)p_qkv;
    float* ctx  = (float*)p_ctx;
    float* xa   = (float*)p_xa;
    float* ffin = (float*)p_ffin;
    float* hid  = (float*)p_hid;
    float* xmlp = (float*)p_xmlp;

    // 1. LN1
    eb_ln_kernel<<<TOKENS, 256>>>(x, ln1_g, ln1_b, xn1);
    // 2. QKV: [16384,768] @ [768,2304] + b
    eb_gemm_kernel<0><<<dim3(QKV_N / GBN, TOKENS / GBM), 256>>>(
        xn1, qkv_w, qkv_b, nullptr, qkv, TOKENS, DIM, QKV_N);
    // 3. attention -> ctx [16384,768]
    eb_attn_kernel<<<dim3(1024 / 64, 16 * HEADS), 128, ATTN_SMEM>>>(qkv, ctx);
    // 4. proj + residual(x): xa = x + ctx @ proj_w + proj_b
    eb_gemm_kernel<1><<<dim3(DIM / GBN, TOKENS / GBM), 256>>>(
        ctx, proj_w, proj_b, x, xa, TOKENS, DIM, DIM);
    // 5. LN2 -> ff_in
    eb_ln_kernel<<<TOKENS, 256>>>(xa, ln2_g, ln2_b, ffin);
    // 6. fc1 + GELU(exact)
    eb_gemm_kernel<2><<<dim3(HIDDEN / GBN, TOKENS / GBM), 256>>>(
        ffin, fc1_w, fc1_b, nullptr, hid, TOKENS, DIM, HIDDEN);
    // 7. fc2 + residual(ff_in)  [reference adds the NORMALIZED tensor]
    eb_gemm_kernel<1><<<dim3(DIM / GBN, TOKENS / GBM), 256>>>(
        hid, fc2_w, fc2_b, ffin, xmlp, TOKENS, HIDDEN, DIM);
    // 8. LN3 -> out
    eb_ln_kernel<<<TOKENS, 256>>>(xmlp, ln3_g, ln3_b, out);
}

// round 6
// speedup vs baseline: 1.5561x; 1.5561x over previous
#include <cuda_runtime.h>
#include <cuda_bf16.h>
#include <cstdint>
#include <math.h>

// ---------------------------------------------------------------------------
// EncoderBlock on GB300 (generic-PTX build): bf16 mma.sync 3-split GEMMs +
// fp32 flash attention. tcgen05 unavailable (harness compiles compute_103).
// ---------------------------------------------------------------------------

#define TOKENS   16384
#define DIM      768
#define HEADS    12
#define HEAD_DIM 64
#define HIDDEN   3072
#define QKV_N    2304
#define LN_EPS   1e-5f

typedef __nv_bfloat16 bf16;

// single extern-shared symbol shared by all dynamic-smem kernels
extern __shared__ __align__(1024) char eb_smem_raw[];

// ----------------------------- scratch (device globals) --------------------
__device__ __align__(256) float g_qkv [TOKENS * QKV_N];
__device__ __align__(256) float g_xa  [TOKENS * DIM];
__device__ __align__(256) float g_ffin[TOKENS * DIM];
__device__ __align__(256) float g_xmlp[TOKENS * DIM];
__device__ __align__(256) bf16  g_bh  [TOKENS * DIM];
__device__ __align__(256) bf16  g_bl  [TOKENS * DIM];
__device__ __align__(256) bf16  g_ah  [TOKENS * HIDDEN];
__device__ __align__(256) bf16  g_al  [TOKENS * HIDDEN];
__device__ __align__(256) bf16  g_wh  [HIDDEN * DIM];
__device__ __align__(256) bf16  g_wl  [HIDDEN * DIM];

// ----------------------------- helpers -------------------------------------
__device__ __forceinline__ uint32_t smem_u32(const void* p) {
    uint32_t a;
    asm("{ .reg .u64 t; cvta.to.shared.u64 t, %1; cvt.u32.u64 %0, t; }"
        : "=r"(a) : "l"(p));
    return a;
}
__device__ __forceinline__ void ldsm4(uint32_t* r, uint32_t addr) {
    asm volatile("ldmatrix.sync.aligned.m8n8.x4.shared.b16 {%0,%1,%2,%3}, [%4];"
                 : "=r"(r[0]), "=r"(r[1]), "=r"(r[2]), "=r"(r[3]) : "r"(addr));
}
__device__ __forceinline__ void mma16816(float* d, const uint32_t* a,
                                         uint32_t b0, uint32_t b1) {
    asm volatile(
        "mma.sync.aligned.m16n8k16.row.col.f32.bf16.bf16.f32 "
        "{%0,%1,%2,%3}, {%4,%5,%6,%7}, {%8,%9}, {%0,%1,%2,%3};"
        : "+f"(d[0]), "+f"(d[1]), "+f"(d[2]), "+f"(d[3])
        : "r"(a[0]), "r"(a[1]), "r"(a[2]), "r"(a[3]), "r"(b0), "r"(b1));
}
#define CP16(dst, src) \
    asm volatile("cp.async.cg.shared.global [%0], [%1], 16;" \
                 :: "r"(dst), "l"(src) : "memory")
#define CP_COMMIT() asm volatile("cp.async.commit_group;" ::: "memory")
template <int N>
__device__ __forceinline__ void cp_wait() {
    asm volatile("cp.async.wait_group %0;" :: "n"(N) : "memory");
}

__device__ __forceinline__ float gelu_exact(float v) {
    return 0.5f * v * (1.0f + erff(v * 0.70710678118654752f));
}
__device__ __forceinline__ void split_f(float v, bf16& h, bf16& l) {
    h = __float2bfloat16(v);
    l = __float2bfloat16(v - __bfloat162float(h));
}

// ----------------------------- LayerNorm -----------------------------------
// OUT: 0 = fp32 only, 1 = bf16 hi/lo only, 2 = both
template <int OUT>
__global__ void eb_ln_kernel(const float* __restrict__ x,
                             const float* __restrict__ g,
                             const float* __restrict__ b,
                             float* __restrict__ y,
                             bf16* __restrict__ yh,
                             bf16* __restrict__ yl) {
    int row = blockIdx.x;
    const float* xr = x + (size_t)row * DIM;
    int t = threadIdx.x;
    float v0 = xr[t], v1 = xr[t + 256], v2 = xr[t + 512];
    float s = v0 + v1 + v2;
    float q = v0 * v0 + v1 * v1 + v2 * v2;
    #pragma unroll
    for (int m = 16; m > 0; m >>= 1) {
        s += __shfl_xor_sync(0xffffffffu, s, m);
        q += __shfl_xor_sync(0xffffffffu, q, m);
    }
    __shared__ float ss[8], sq[8];
    __shared__ float mean_s, rstd_s;
    int w = t >> 5, lane = t & 31;
    if (lane == 0) { ss[w] = s; sq[w] = q; }
    __syncthreads();
    if (t == 0) {
        float S = 0.f, Q = 0.f;
        #pragma unroll
        for (int i = 0; i < 8; i++) { S += ss[i]; Q += sq[i]; }
        float mean = S * (1.0f / DIM);
        float var  = Q * (1.0f / DIM) - mean * mean;
        mean_s = mean;
        rstd_s = rsqrtf(var + LN_EPS);
    }
    __syncthreads();
    float mean = mean_s, rstd = rstd_s;
    size_t base = (size_t)row * DIM;
    #pragma unroll
    for (int i = 0; i < 3; i++) {
        int c = t + i * 256;
        float v = (i == 0 ? v0 : (i == 1 ? v1 : v2));
        float o = (v - mean) * rstd * g[c] + b[c];
        if (OUT != 1) y[base + c] = o;
        if (OUT != 0) split_f(o, yh[base + c], yl[base + c]);
    }
}

// ----------------------------- weight transpose + split --------------------
// W [K][N] fp32 -> wt_hi/lo [N][K] bf16
__global__ void eb_wsplit_kernel(const float* __restrict__ W,
                                 bf16* __restrict__ th, bf16* __restrict__ tl,
                                 int K, int N) {
    __shared__ float s[32][33];
    int tx = threadIdx.x, ty = threadIdx.y;
    int n0 = blockIdx.x * 32, k0 = blockIdx.y * 32;
    #pragma unroll
    for (int r = 0; r < 4; r++)
        s[ty + 8 * r][tx] = W[(size_t)(k0 + ty + 8 * r) * N + n0 + tx];
    __syncthreads();
    #pragma unroll
    for (int r = 0; r < 4; r++) {
        float v = s[tx][ty + 8 * r];
        size_t idx = (size_t)(n0 + ty + 8 * r) * K + k0 + tx;
        split_f(v, th[idx], tl[idx]);
    }
}

// ----------------------------- bf16 mma.sync 3-split GEMM ------------------
// C[M,N] = epi(sum_k (Ah+Al)[m,k]*(Wh+Wl)[n,k] + bias)
// Tile 128x128x32, 256 thr (2x4 warps, warp tile 64x32), cp.async dbl-buffer.
// smem per operand tile: 128 rows x 64B, chunk swizzle: c ^= (row>>1)&3.
// EPI: 0 = bias -> fp32; 1 = bias + residual -> fp32; 2 = bias+GELU -> hi/lo
#define OPB   8192            // 128 * 64
#define BUFB  (4 * OPB)       // Ah Al Wh Wl
#define MM_SMEM (2 * BUFB)    // 64 KB

template <int EPI>
__global__ __launch_bounds__(256, 1)
void eb_mma_gemm(const bf16* __restrict__ Ah, const bf16* __restrict__ Al,
                 const bf16* __restrict__ Wh, const bf16* __restrict__ Wl,
                 const float* __restrict__ bias, const float* __restrict__ R,
                 float* __restrict__ Cf, bf16* __restrict__ Ch,
                 bf16* __restrict__ Cl, int K, int N) {
    uint32_t su = smem_u32(eb_smem_raw);
    int tid = threadIdx.x;
    int lane = tid & 31, wid = tid >> 5;
    int wm = wid >> 2, wn = wid & 3;      // 2 x 4 warp grid
    int m0 = blockIdx.y * 128, n0 = blockIdx.x * 128;

    // --- async copy geometry: thread -> (row, 2 chunks of 16B) per operand
    int crow = tid >> 1;                  // 0..127
    int cc0  = (tid & 1) * 2;             // chunk 0 or 2
    uint32_t sw   = (uint32_t)((crow >> 1) & 3);
    uint32_t rel0 = crow * 64 + ((cc0 ^ sw) * 16);
    uint32_t rel1 = crow * 64 + (((cc0 + 1) ^ sw) * 16);
    const bf16* gA0 = Ah + (size_t)(m0 + crow) * K + cc0 * 8;
    const bf16* gA1 = Al + (size_t)(m0 + crow) * K + cc0 * 8;
    const bf16* gW0 = Wh + (size_t)(n0 + crow) * K + cc0 * 8;
    const bf16* gW1 = Wl + (size_t)(n0 + crow) * K + cc0 * 8;

    float acc[4][4][4];
    #pragma unroll
    for (int i = 0; i < 4; i++)
        #pragma unroll
        for (int j = 0; j < 4; j++)
            #pragma unroll
            for (int r = 0; r < 4; r++) acc[i][j][r] = 0.f;

    auto issue = [&](int buf, int koff) {
        uint32_t b = su + buf * BUFB;
        CP16(b + rel0,           gA0 + koff);
        CP16(b + rel1,           gA0 + koff + 8);
        CP16(b + OPB + rel0,     gA1 + koff);
        CP16(b + OPB + rel1,     gA1 + koff + 8);
        CP16(b + 2 * OPB + rel0, gW0 + koff);
        CP16(b + 2 * OPB + rel1, gW0 + koff + 8);
        CP16(b + 3 * OPB + rel0, gW1 + koff);
        CP16(b + 3 * OPB + rel1, gW1 + koff + 8);
    };

    // ldmatrix addresses: row r, k-chunk = 2s + (lane>>4)
    int lrow = lane & 15;
    int lhalf = lane >> 4;

    int NK = K >> 5;
    issue(0, 0);
    CP_COMMIT();

    for (int kt = 0; kt < NK; kt++) {
        if (kt + 1 < NK) {
            issue((kt + 1) & 1, (kt + 1) * 32);
            CP_COMMIT();
            cp_wait<1>();
        } else {
            cp_wait<0>();
        }
        __syncthreads();
        uint32_t bb = su + (kt & 1) * BUFB;

        #pragma unroll
        for (int s = 0; s < 2; s++) {
            uint32_t af[4][4], alf[4][4];
            #pragma unroll
            for (int mt = 0; mt < 4; mt++) {
                int r = wm * 64 + mt * 16 + lrow;
                int ch = 2 * s + lhalf;
                uint32_t ad = bb + r * 64 + ((ch ^ ((r >> 1) & 3)) * 16);
                ldsm4(af[mt], ad);
                ldsm4(alf[mt], ad + OPB);
            }
            uint32_t bh[2][4], bl[2][4];
            #pragma unroll
            for (int g = 0; g < 2; g++) {
                int r = wn * 32 + g * 16 + lrow;
                int ch = 2 * s + lhalf;
                uint32_t ad = bb + 2 * OPB + r * 64 + ((ch ^ ((r >> 1) & 3)) * 16);
                ldsm4(bh[g], ad);
                ldsm4(bl[g], ad + OPB);
            }
            #pragma unroll
            for (int mt = 0; mt < 4; mt++) {
                #pragma unroll
                for (int nt = 0; nt < 4; nt++) {
                    int g = nt >> 1, sel = nt & 1;
                    uint32_t b0h = bh[g][sel], b1h = bh[g][sel + 2];
                    uint32_t b0l = bl[g][sel], b1l = bl[g][sel + 2];
                    mma16816(acc[mt][nt], af[mt],  b0h, b1h);
                    mma16816(acc[mt][nt], af[mt],  b0l, b1l);
                    mma16816(acc[mt][nt], alf[mt], b0h, b1h);
                }
            }
        }
        __syncthreads();
    }

    // --- epilogue: C fragment (row g=lane>>2 [+8], col (lane&3)*2 [+1])
    int grp = lane >> 2, qc = (lane & 3) * 2;
    #pragma unroll
    for (int mt = 0; mt < 4; mt++) {
        int row0 = m0 + wm * 64 + mt * 16 + grp;
        #pragma unroll
        for (int nt = 0; nt < 4; nt++) {
            int col = n0 + wn * 32 + nt * 8 + qc;
            float bx = bias[col], by = bias[col + 1];
            #pragma unroll
            for (int hrow = 0; hrow < 2; hrow++) {
                int row = row0 + hrow * 8;
                float vx = acc[mt][nt][hrow * 2]     + bx;
                float vy = acc[mt][nt][hrow * 2 + 1] + by;
                size_t idx = (size_t)row * N + col;
                if (EPI == 2) {
                    vx = gelu_exact(vx); vy = gelu_exact(vy);
                    bf16 h0, l0, h1, l1;
                    split_f(vx, h0, l0); split_f(vy, h1, l1);
                    *(__nv_bfloat162*)(Ch + idx) = __nv_bfloat162(h0, h1);
                    *(__nv_bfloat162*)(Cl + idx) = __nv_bfloat162(l0, l1);
                } else {
                    if (EPI == 1) {
                        float2 rr = *(const float2*)(R + idx);
                        vx += rr.x; vy += rr.y;
                    }
                    *(float2*)(Cf + idx) = make_float2(vx, vy);
                }
            }
        }
    }
}

// ----------------------------- flash attention (fp32, split output) --------
#define APAD 68
#define ATTN_SMEM (3 * 64 * APAD * 4)

__global__ __launch_bounds__(128, 4)
void eb_attn_kernel(const float* __restrict__ qkv,
                    bf16* __restrict__ ch, bf16* __restrict__ cl) {
    float* smem = (float*)eb_smem_raw;
    float (*Qt)[APAD] = (float(*)[APAD])(smem);
    float (*KP)[APAD] = (float(*)[APAD])(smem + 64 * APAD);
    float (*Vs)[APAD] = (float(*)[APAD])(smem + 2 * 64 * APAD);

    int tid = threadIdx.x;
    int tx = tid & 15;
    int ty = tid >> 4;
    int bh = blockIdx.y;
    int b = bh / HEADS, h = bh % HEADS;
    int q0 = blockIdx.x * 64;
    size_t rowbase = (size_t)b * 1024;
    const int LD = QKV_N;
    int qoff = h * HEAD_DIM;
    int koff = DIM + h * HEAD_DIM;
    int voff = 2 * DIM + h * HEAD_DIM;

    {
        int r = tid >> 1;
        int cb = (tid & 1) * 32;
        #pragma unroll
        for (int i = 0; i < 8; i++) {
            int c = cb + i * 4;
            float4 v = *(const float4*)&qkv[(rowbase + q0 + r) * LD + qoff + c];
            Qt[c + 0][r] = v.x * 0.125f; Qt[c + 1][r] = v.y * 0.125f;
            Qt[c + 2][r] = v.z * 0.125f; Qt[c + 3][r] = v.w * 0.125f;
        }
    }

    float acc[8][4];
    float m_run[8], l_run[8];
    #pragma unroll
    for (int i = 0; i < 8; i++) {
        m_run[i] = -3.0e38f; l_run[i] = 0.f;
        #pragma unroll
        for (int j = 0; j < 4; j++) acc[i][j] = 0.f;
    }

    for (int kt = 0; kt < 16; kt++) {
        int kr0 = kt * 64;
        __syncthreads();
        {
            int r = tid >> 1;
            int cb = (tid & 1) * 32;
            #pragma unroll
            for (int i = 0; i < 8; i++) {
                int c = cb + i * 4;
                float4 v = *(const float4*)&qkv[(rowbase + kr0 + r) * LD + koff + c];
                KP[c + 0][r] = v.x; KP[c + 1][r] = v.y;
                KP[c + 2][r] = v.z; KP[c + 3][r] = v.w;
                float4 w = *(const float4*)&qkv[(rowbase + kr0 + r) * LD + voff + c];
                *(float4*)&Vs[r][c] = w;
            }
        }
        __syncthreads();

        float s[8][4];
        #pragma unroll
        for (int i = 0; i < 8; i++)
            #pragma unroll
            for (int j = 0; j < 4; j++) s[i][j] = 0.f;
        #pragma unroll 4
        for (int d = 0; d < 64; d++) {
            float4 aA = *(const float4*)&Qt[d][ty * 8];
            float4 aB = *(const float4*)&Qt[d][ty * 8 + 4];
            float4 bb = *(const float4*)&KP[d][tx * 4];
            float a[8] = {aA.x, aA.y, aA.z, aA.w, aB.x, aB.y, aB.z, aB.w};
            #pragma unroll
            for (int i = 0; i < 8; i++) {
                s[i][0] = fmaf(a[i], bb.x, s[i][0]);
                s[i][1] = fmaf(a[i], bb.y, s[i][1]);
                s[i][2] = fmaf(a[i], bb.z, s[i][2]);
                s[i][3] = fmaf(a[i], bb.w, s[i][3]);
            }
        }
        __syncthreads();

        #pragma unroll
        for (int i = 0; i < 8; i++) {
            float tm = fmaxf(fmaxf(s[i][0], s[i][1]), fmaxf(s[i][2], s[i][3]));
            tm = fmaxf(tm, __shfl_xor_sync(0xffffffffu, tm, 1));
            tm = fmaxf(tm, __shfl_xor_sync(0xffffffffu, tm, 2));
            tm = fmaxf(tm, __shfl_xor_sync(0xffffffffu, tm, 4));
            tm = fmaxf(tm, __shfl_xor_sync(0xffffffffu, tm, 8));
            float mn = fmaxf(m_run[i], tm);
            float sc = __expf(m_run[i] - mn);
            float ps = 0.f;
            #pragma unroll
            for (int j = 0; j < 4; j++) {
                float p = __expf(s[i][j] - mn);
                s[i][j] = p;
                ps += p;
            }
            ps += __shfl_xor_sync(0xffffffffu, ps, 1);
            ps += __shfl_xor_sync(0xffffffffu, ps, 2);
            ps += __shfl_xor_sync(0xffffffffu, ps, 4);
            ps += __shfl_xor_sync(0xffffffffu, ps, 8);
            l_run[i] = l_run[i] * sc + ps;
            m_run[i] = mn;
            #pragma unroll
            for (int j = 0; j < 4; j++) acc[i][j] *= sc;
            *(float4*)&KP[ty * 8 + i][tx * 4] =
                make_float4(s[i][0], s[i][1], s[i][2], s[i][3]);
        }
        __syncthreads();

        #pragma unroll 4
        for (int c = 0; c < 64; c++) {
            float4 bb = *(const float4*)&Vs[c][tx * 4];
            #pragma unroll
            for (int i = 0; i < 8; i++) {
                float p = KP[ty * 8 + i][c];
                acc[i][0] = fmaf(p, bb.x, acc[i][0]);
                acc[i][1] = fmaf(p, bb.y, acc[i][1]);
                acc[i][2] = fmaf(p, bb.z, acc[i][2]);
                acc[i][3] = fmaf(p, bb.w, acc[i][3]);
            }
        }
    }

    #pragma unroll
    for (int i = 0; i < 8; i++) {
        float inv = 1.0f / l_run[i];
        size_t idx = (rowbase + q0 + ty * 8 + i) * DIM + h * HEAD_DIM + tx * 4;
        bf16 h0, l0, h1, l1;
        split_f(acc[i][0] * inv, h0, l0);
        split_f(acc[i][1] * inv, h1, l1);
        *(__nv_bfloat162*)(ch + idx) = __nv_bfloat162(h0, h1);
        *(__nv_bfloat162*)(cl + idx) = __nv_bfloat162(l0, l1);
        split_f(acc[i][2] * inv, h0, l0);
        split_f(acc[i][3] * inv, h1, l1);
        *(__nv_bfloat162*)(ch + idx + 2) = __nv_bfloat162(h0, h1);
        *(__nv_bfloat162*)(cl + idx + 2) = __nv_bfloat162(l0, l1);
    }
}

// ----------------------------- launch ---------------------------------------
extern "C" void kernel_launch(void* const* d_in, const int* in_sizes, int n_in,
                              void* d_out, int out_size) {
    const float* x      = (const float*)d_in[0];
    const float* ln1_g  = (const float*)d_in[1];
    const float* ln1_b  = (const float*)d_in[2];
    const float* qkv_w  = (const float*)d_in[3];
    const float* qkv_b  = (const float*)d_in[4];
    const float* proj_w = (const float*)d_in[5];
    const float* proj_b = (const float*)d_in[6];
    const float* ln2_g  = (const float*)d_in[7];
    const float* ln2_b  = (const float*)d_in[8];
    const float* fc1_w  = (const float*)d_in[9];
    const float* fc1_b  = (const float*)d_in[10];
    const float* fc2_w  = (const float*)d_in[11];
    const float* fc2_b  = (const float*)d_in[12];
    const float* ln3_g  = (const float*)d_in[13];
    const float* ln3_b  = (const float*)d_in[14];
    float* out = (float*)d_out;

    void *p;
    cudaGetSymbolAddress(&p, g_qkv);  float* qkv  = (float*)p;
    cudaGetSymbolAddress(&p, g_xa);   float* xa   = (float*)p;
    cudaGetSymbolAddress(&p, g_ffin); float* ffin = (float*)p;
    cudaGetSymbolAddress(&p, g_xmlp); float* xmlp = (float*)p;
    cudaGetSymbolAddress(&p, g_bh);   bf16* bh = (bf16*)p;
    cudaGetSymbolAddress(&p, g_bl);   bf16* bl = (bf16*)p;
    cudaGetSymbolAddress(&p, g_ah);   bf16* ah = (bf16*)p;
    cudaGetSymbolAddress(&p, g_al);   bf16* al = (bf16*)p;
    cudaGetSymbolAddress(&p, g_wh);   bf16* wh = (bf16*)p;
    cudaGetSymbolAddress(&p, g_wl);   bf16* wl = (bf16*)p;

    cudaFuncSetAttribute(eb_attn_kernel,
                         cudaFuncAttributeMaxDynamicSharedMemorySize, ATTN_SMEM);
    cudaFuncSetAttribute(eb_mma_gemm<0>,
                         cudaFuncAttributeMaxDynamicSharedMemorySize, MM_SMEM);
    cudaFuncSetAttribute(eb_mma_gemm<1>,
                         cudaFuncAttributeMaxDynamicSharedMemorySize, MM_SMEM);
    cudaFuncSetAttribute(eb_mma_gemm<2>,
                         cudaFuncAttributeMaxDynamicSharedMemorySize, MM_SMEM);

    dim3 wsb(32, 8);

    // 1. LN1 -> split activations (bh/bl)
    eb_ln_kernel<1><<<TOKENS, 256>>>(x, ln1_g, ln1_b, nullptr, bh, bl);
    // 2. QKV
    eb_wsplit_kernel<<<dim3(QKV_N / 32, DIM / 32), wsb>>>(qkv_w, wh, wl, DIM, QKV_N);
    eb_mma_gemm<0><<<dim3(QKV_N / 128, TOKENS / 128), 256, MM_SMEM>>>(
        bh, bl, wh, wl, qkv_b, nullptr, qkv, nullptr, nullptr, DIM, QKV_N);
    // 3. attention -> ctx split (bh/bl)
    eb_attn_kernel<<<dim3(1024 / 64, 16 * HEADS), 128, ATTN_SMEM>>>(qkv, bh, bl);
    // 4. proj + residual(x)
    eb_wsplit_kernel<<<dim3(DIM / 32, DIM / 32), wsb>>>(proj_w, wh, wl, DIM, DIM);
    eb_mma_gemm<1><<<dim3(DIM / 128, TOKENS / 128), 256, MM_SMEM>>>(
        bh, bl, wh, wl, proj_b, x, xa, nullptr, nullptr, DIM, DIM);
    // 5. LN2 -> ffin fp32 + split (bh/bl)
    eb_ln_kernel<2><<<TOKENS, 256>>>(xa, ln2_g, ln2_b, ffin, bh, bl);
    // 6. fc1 + GELU -> hid split (ah/al)
    eb_wsplit_kernel<<<dim3(HIDDEN / 32, DIM / 32), wsb>>>(fc1_w, wh, wl, DIM, HIDDEN);
    eb_mma_gemm<2><<<dim3(HIDDEN / 128, TOKENS / 128), 256, MM_SMEM>>>(
        bh, bl, wh, wl, fc1_b, nullptr, nullptr, ah, al, DIM, HIDDEN);
    // 7. fc2 + residual(ffin)  [reference adds the NORMALIZED tensor]
    eb_wsplit_kernel<<<dim3(DIM / 32, HIDDEN / 32), wsb>>>(fc2_w, wh, wl, HIDDEN, DIM);
    eb_mma_gemm<1><<<dim3(DIM / 128, TOKENS / 128), 256, MM_SMEM>>>(
        ah, al, wh, wl, fc2_b, ffin, xmlp, nullptr, nullptr, HIDDEN, DIM);
    // 8. LN3 -> out
    eb_ln_kernel<0><<<TOKENS, 256>>>(xmlp, ln3_g, ln3_b, out, nullptr, nullptr);
}

// round 7
// speedup vs baseline: 1.6275x; 1.0459x over previous
#include <cuda_runtime.h>
#include <cuda_bf16.h>
#include <cstdint>
#include <math.h>

// ---------------------------------------------------------------------------
// EncoderBlock on GB300 (generic-PTX build): bf16 mma.sync 3-split GEMMs (occ 2)
// + fp32 flash attention with f32x2 packed FFMA.
// ---------------------------------------------------------------------------

#define TOKENS   16384
#define DIM      768
#define HEADS    12
#define HEAD_DIM 64
#define HIDDEN   3072
#define QKV_N    2304
#define LN_EPS   1e-5f

typedef __nv_bfloat16 bf16;

// single extern-shared symbol shared by all dynamic-smem kernels
extern __shared__ __align__(1024) char eb_smem_raw[];

// ----------------------------- scratch (device globals) --------------------
__device__ __align__(256) float g_qkv [TOKENS * QKV_N];
__device__ __align__(256) float g_xa  [TOKENS * DIM];
__device__ __align__(256) float g_ffin[TOKENS * DIM];
__device__ __align__(256) float g_xmlp[TOKENS * DIM];
__device__ __align__(256) bf16  g_bh  [TOKENS * DIM];
__device__ __align__(256) bf16  g_bl  [TOKENS * DIM];
__device__ __align__(256) bf16  g_ah  [TOKENS * HIDDEN];
__device__ __align__(256) bf16  g_al  [TOKENS * HIDDEN];
__device__ __align__(256) bf16  g_wh  [HIDDEN * DIM];
__device__ __align__(256) bf16  g_wl  [HIDDEN * DIM];

// ----------------------------- helpers -------------------------------------
__device__ __forceinline__ uint32_t smem_u32(const void* p) {
    uint32_t a;
    asm("{ .reg .u64 t; cvta.to.shared.u64 t, %1; cvt.u32.u64 %0, t; }"
        : "=r"(a) : "l"(p));
    return a;
}
__device__ __forceinline__ void ldsm4(uint32_t* r, uint32_t addr) {
    asm volatile("ldmatrix.sync.aligned.m8n8.x4.shared.b16 {%0,%1,%2,%3}, [%4];"
                 : "=r"(r[0]), "=r"(r[1]), "=r"(r[2]), "=r"(r[3]) : "r"(addr));
}
__device__ __forceinline__ void mma16816(float* d, const uint32_t* a,
                                         uint32_t b0, uint32_t b1) {
    asm volatile(
        "mma.sync.aligned.m16n8k16.row.col.f32.bf16.bf16.f32 "
        "{%0,%1,%2,%3}, {%4,%5,%6,%7}, {%8,%9}, {%0,%1,%2,%3};"
        : "+f"(d[0]), "+f"(d[1]), "+f"(d[2]), "+f"(d[3])
        : "r"(a[0]), "r"(a[1]), "r"(a[2]), "r"(a[3]), "r"(b0), "r"(b1));
}
#define CP16(dst, src) \
    asm volatile("cp.async.cg.shared.global [%0], [%1], 16;" \
                 :: "r"(dst), "l"(src) : "memory")
#define CP_COMMIT() asm volatile("cp.async.commit_group;" ::: "memory")
template <int N>
__device__ __forceinline__ void cp_wait() {
    asm volatile("cp.async.wait_group %0;" :: "n"(N) : "memory");
}

// ---- f32x2 packed fp32 (sm_103a dual-issue FFMA) ----
__device__ __forceinline__ unsigned long long frep2(float a) {
    unsigned long long r;
    unsigned ia = __float_as_uint(a);
    asm("mov.b64 %0, {%1,%2};" : "=l"(r) : "r"(ia), "r"(ia));
    return r;
}
__device__ __forceinline__ void ffma2(unsigned long long& d,
                                      unsigned long long a,
                                      unsigned long long b) {
    asm("fma.rn.f32x2 %0, %1, %2, %0;" : "+l"(d) : "l"(a), "l"(b));
}
__device__ __forceinline__ void fmul2(unsigned long long& d,
                                      unsigned long long a) {
    asm("mul.rn.f32x2 %0, %0, %1;" : "+l"(d) : "l"(a));
}
__device__ __forceinline__ float2 funpack2(unsigned long long v) {
    unsigned lo, hi;
    asm("mov.b64 {%0,%1}, %2;" : "=r"(lo), "=r"(hi) : "l"(v));
    return make_float2(__uint_as_float(lo), __uint_as_float(hi));
}

__device__ __forceinline__ float gelu_exact(float v) {
    return 0.5f * v * (1.0f + erff(v * 0.70710678118654752f));
}
__device__ __forceinline__ void split_f(float v, bf16& h, bf16& l) {
    h = __float2bfloat16(v);
    l = __float2bfloat16(v - __bfloat162float(h));
}

// ----------------------------- LayerNorm -----------------------------------
// OUT: 0 = fp32 only, 1 = bf16 hi/lo only, 2 = both
template <int OUT>
__global__ void eb_ln_kernel(const float* __restrict__ x,
                             const float* __restrict__ g,
                             const float* __restrict__ b,
                             float* __restrict__ y,
                             bf16* __restrict__ yh,
                             bf16* __restrict__ yl) {
    int row = blockIdx.x;
    const float* xr = x + (size_t)row * DIM;
    int t = threadIdx.x;
    float v0 = xr[t], v1 = xr[t + 256], v2 = xr[t + 512];
    float s = v0 + v1 + v2;
    float q = v0 * v0 + v1 * v1 + v2 * v2;
    #pragma unroll
    for (int m = 16; m > 0; m >>= 1) {
        s += __shfl_xor_sync(0xffffffffu, s, m);
        q += __shfl_xor_sync(0xffffffffu, q, m);
    }
    __shared__ float ss[8], sq[8];
    __shared__ float mean_s, rstd_s;
    int w = t >> 5, lane = t & 31;
    if (lane == 0) { ss[w] = s; sq[w] = q; }
    __syncthreads();
    if (t == 0) {
        float S = 0.f, Q = 0.f;
        #pragma unroll
        for (int i = 0; i < 8; i++) { S += ss[i]; Q += sq[i]; }
        float mean = S * (1.0f / DIM);
        float var  = Q * (1.0f / DIM) - mean * mean;
        mean_s = mean;
        rstd_s = rsqrtf(var + LN_EPS);
    }
    __syncthreads();
    float mean = mean_s, rstd = rstd_s;
    size_t base = (size_t)row * DIM;
    #pragma unroll
    for (int i = 0; i < 3; i++) {
        int c = t + i * 256;
        float v = (i == 0 ? v0 : (i == 1 ? v1 : v2));
        float o = (v - mean) * rstd * g[c] + b[c];
        if (OUT != 1) y[base + c] = o;
        if (OUT != 0) split_f(o, yh[base + c], yl[base + c]);
    }
}

// ----------------------------- weight transpose + split --------------------
__global__ void eb_wsplit_kernel(const float* __restrict__ W,
                                 bf16* __restrict__ th, bf16* __restrict__ tl,
                                 int K, int N) {
    __shared__ float s[32][33];
    int tx = threadIdx.x, ty = threadIdx.y;
    int n0 = blockIdx.x * 32, k0 = blockIdx.y * 32;
    #pragma unroll
    for (int r = 0; r < 4; r++)
        s[ty + 8 * r][tx] = W[(size_t)(k0 + ty + 8 * r) * N + n0 + tx];
    __syncthreads();
    #pragma unroll
    for (int r = 0; r < 4; r++) {
        float v = s[tx][ty + 8 * r];
        size_t idx = (size_t)(n0 + ty + 8 * r) * K + k0 + tx;
        split_f(v, th[idx], tl[idx]);
    }
}

// ----------------------------- bf16 mma.sync 3-split GEMM ------------------
// Tile 128x128x32, 256 thr (2x4 warps, warp tile 64x32), cp.async dbl-buffer,
// 2 CTAs/SM for latency hiding.
#define OPB   8192
#define BUFB  (4 * OPB)
#define MM_SMEM (2 * BUFB)    // 64 KB per CTA

template <int EPI>
__global__ __launch_bounds__(256, 2)
void eb_mma_gemm(const bf16* __restrict__ Ah, const bf16* __restrict__ Al,
                 const bf16* __restrict__ Wh, const bf16* __restrict__ Wl,
                 const float* __restrict__ bias, const float* __restrict__ R,
                 float* __restrict__ Cf, bf16* __restrict__ Ch,
                 bf16* __restrict__ Cl, int K, int N) {
    uint32_t su = smem_u32(eb_smem_raw);
    int tid = threadIdx.x;
    int lane = tid & 31, wid = tid >> 5;
    int wm = wid >> 2, wn = wid & 3;
    int m0 = blockIdx.y * 128, n0 = blockIdx.x * 128;

    int crow = tid >> 1;
    int cc0  = (tid & 1) * 2;
    uint32_t sw   = (uint32_t)((crow >> 1) & 3);
    uint32_t rel0 = crow * 64 + ((cc0 ^ sw) * 16);
    uint32_t rel1 = crow * 64 + (((cc0 + 1) ^ sw) * 16);
    const bf16* gA0 = Ah + (size_t)(m0 + crow) * K + cc0 * 8;
    const bf16* gA1 = Al + (size_t)(m0 + crow) * K + cc0 * 8;
    const bf16* gW0 = Wh + (size_t)(n0 + crow) * K + cc0 * 8;
    const bf16* gW1 = Wl + (size_t)(n0 + crow) * K + cc0 * 8;

    float acc[4][4][4];
    #pragma unroll
    for (int i = 0; i < 4; i++)
        #pragma unroll
        for (int j = 0; j < 4; j++)
            #pragma unroll
            for (int r = 0; r < 4; r++) acc[i][j][r] = 0.f;

    auto issue = [&](int buf, int koff) {
        uint32_t b = su + buf * BUFB;
        CP16(b + rel0,           gA0 + koff);
        CP16(b + rel1,           gA0 + koff + 8);
        CP16(b + OPB + rel0,     gA1 + koff);
        CP16(b + OPB + rel1,     gA1 + koff + 8);
        CP16(b + 2 * OPB + rel0, gW0 + koff);
        CP16(b + 2 * OPB + rel1, gW0 + koff + 8);
        CP16(b + 3 * OPB + rel0, gW1 + koff);
        CP16(b + 3 * OPB + rel1, gW1 + koff + 8);
    };

    int lrow = lane & 15;
    int lhalf = lane >> 4;

    int NK = K >> 5;
    issue(0, 0);
    CP_COMMIT();

    for (int kt = 0; kt < NK; kt++) {
        if (kt + 1 < NK) {
            issue((kt + 1) & 1, (kt + 1) * 32);
            CP_COMMIT();
            cp_wait<1>();
        } else {
            cp_wait<0>();
        }
        __syncthreads();
        uint32_t bb = su + (kt & 1) * BUFB;

        #pragma unroll
        for (int s = 0; s < 2; s++) {
            uint32_t af[4][4], alf[4][4];
            #pragma unroll
            for (int mt = 0; mt < 4; mt++) {
                int r = wm * 64 + mt * 16 + lrow;
                int ch = 2 * s + lhalf;
                uint32_t ad = bb + r * 64 + ((ch ^ ((r >> 1) & 3)) * 16);
                ldsm4(af[mt], ad);
                ldsm4(alf[mt], ad + OPB);
            }
            uint32_t bh[2][4], bl[2][4];
            #pragma unroll
            for (int g = 0; g < 2; g++) {
                int r = wn * 32 + g * 16 + lrow;
                int ch = 2 * s + lhalf;
                uint32_t ad = bb + 2 * OPB + r * 64 + ((ch ^ ((r >> 1) & 3)) * 16);
                ldsm4(bh[g], ad);
                ldsm4(bl[g], ad + OPB);
            }
            #pragma unroll
            for (int mt = 0; mt < 4; mt++) {
                #pragma unroll
                for (int nt = 0; nt < 4; nt++) {
                    int g = nt >> 1, sel = nt & 1;
                    uint32_t b0h = bh[g][sel], b1h = bh[g][sel + 2];
                    uint32_t b0l = bl[g][sel], b1l = bl[g][sel + 2];
                    mma16816(acc[mt][nt], af[mt],  b0h, b1h);
                    mma16816(acc[mt][nt], af[mt],  b0l, b1l);
                    mma16816(acc[mt][nt], alf[mt], b0h, b1h);
                }
            }
        }
        __syncthreads();
    }

    int grp = lane >> 2, qc = (lane & 3) * 2;
    #pragma unroll
    for (int mt = 0; mt < 4; mt++) {
        int row0 = m0 + wm * 64 + mt * 16 + grp;
        #pragma unroll
        for (int nt = 0; nt < 4; nt++) {
            int col = n0 + wn * 32 + nt * 8 + qc;
            float bx = bias[col], by = bias[col + 1];
            #pragma unroll
            for (int hrow = 0; hrow < 2; hrow++) {
                int row = row0 + hrow * 8;
                float vx = acc[mt][nt][hrow * 2]     + bx;
                float vy = acc[mt][nt][hrow * 2 + 1] + by;
                size_t idx = (size_t)row * N + col;
                if (EPI == 2) {
                    vx = gelu_exact(vx); vy = gelu_exact(vy);
                    bf16 h0, l0, h1, l1;
                    split_f(vx, h0, l0); split_f(vy, h1, l1);
                    *(__nv_bfloat162*)(Ch + idx) = __nv_bfloat162(h0, h1);
                    *(__nv_bfloat162*)(Cl + idx) = __nv_bfloat162(l0, l1);
                } else {
                    if (EPI == 1) {
                        float2 rr = *(const float2*)(R + idx);
                        vx += rr.x; vy += rr.y;
                    }
                    *(float2*)(Cf + idx) = make_float2(vx, vy);
                }
            }
        }
    }
}

// ----------------------------- flash attention (fp32 + f32x2 FFMA) ---------
#define APAD 68
#define ATTN_SMEM (3 * 64 * APAD * 4)

__global__ __launch_bounds__(128, 4)
void eb_attn_kernel(const float* __restrict__ qkv,
                    bf16* __restrict__ ch, bf16* __restrict__ cl) {
    float* smem = (float*)eb_smem_raw;
    float (*Qt)[APAD] = (float(*)[APAD])(smem);
    float (*KP)[APAD] = (float(*)[APAD])(smem + 64 * APAD);
    float (*Vs)[APAD] = (float(*)[APAD])(smem + 2 * 64 * APAD);

    int tid = threadIdx.x;
    int tx = tid & 15;
    int ty = tid >> 4;
    int bh = blockIdx.y;
    int b = bh / HEADS, h = bh % HEADS;
    int q0 = blockIdx.x * 64;
    size_t rowbase = (size_t)b * 1024;
    const int LD = QKV_N;
    int qoff = h * HEAD_DIM;
    int koff = DIM + h * HEAD_DIM;
    int voff = 2 * DIM + h * HEAD_DIM;

    {
        int r = tid >> 1;
        int cb = (tid & 1) * 32;
        #pragma unroll
        for (int i = 0; i < 8; i++) {
            int c = cb + i * 4;
            float4 v = *(const float4*)&qkv[(rowbase + q0 + r) * LD + qoff + c];
            Qt[c + 0][r] = v.x * 0.125f; Qt[c + 1][r] = v.y * 0.125f;
            Qt[c + 2][r] = v.z * 0.125f; Qt[c + 3][r] = v.w * 0.125f;
        }
    }

    unsigned long long accp[8][2];   // packed fp32 pairs
    float m_run[8], l_run[8];
    #pragma unroll
    for (int i = 0; i < 8; i++) {
        m_run[i] = -3.0e38f; l_run[i] = 0.f;
        accp[i][0] = 0ull; accp[i][1] = 0ull;
    }

    for (int kt = 0; kt < 16; kt++) {
        int kr0 = kt * 64;
        __syncthreads();
        {
            int r = tid >> 1;
            int cb = (tid & 1) * 32;
            #pragma unroll
            for (int i = 0; i < 8; i++) {
                int c = cb + i * 4;
                float4 v = *(const float4*)&qkv[(rowbase + kr0 + r) * LD + koff + c];
                KP[c + 0][r] = v.x; KP[c + 1][r] = v.y;
                KP[c + 2][r] = v.z; KP[c + 3][r] = v.w;
                float4 w = *(const float4*)&qkv[(rowbase + kr0 + r) * LD + voff + c];
                *(float4*)&Vs[r][c] = w;
            }
        }
        __syncthreads();

        // S tile via packed FFMA2: sp[i] = {s0,s1},{s2,s3}
        unsigned long long sp[8][2];
        #pragma unroll
        for (int i = 0; i < 8; i++) { sp[i][0] = 0ull; sp[i][1] = 0ull; }
        #pragma unroll 4
        for (int d = 0; d < 64; d++) {
            float4 aA = *(const float4*)&Qt[d][ty * 8];
            float4 aB = *(const float4*)&Qt[d][ty * 8 + 4];
            ulonglong2 bu = *(const ulonglong2*)&KP[d][tx * 4];
            float a[8] = {aA.x, aA.y, aA.z, aA.w, aB.x, aB.y, aB.z, aB.w};
            #pragma unroll
            for (int i = 0; i < 8; i++) {
                unsigned long long ar = frep2(a[i]);
                ffma2(sp[i][0], ar, bu.x);
                ffma2(sp[i][1], ar, bu.y);
            }
        }
        __syncthreads();

        #pragma unroll
        for (int i = 0; i < 8; i++) {
            float2 s01 = funpack2(sp[i][0]);
            float2 s23 = funpack2(sp[i][1]);
            float tm = fmaxf(fmaxf(s01.x, s01.y), fmaxf(s23.x, s23.y));
            tm = fmaxf(tm, __shfl_xor_sync(0xffffffffu, tm, 1));
            tm = fmaxf(tm, __shfl_xor_sync(0xffffffffu, tm, 2));
            tm = fmaxf(tm, __shfl_xor_sync(0xffffffffu, tm, 4));
            tm = fmaxf(tm, __shfl_xor_sync(0xffffffffu, tm, 8));
            float mn = fmaxf(m_run[i], tm);
            float sc = __expf(m_run[i] - mn);
            float p0 = __expf(s01.x - mn), p1 = __expf(s01.y - mn);
            float p2 = __expf(s23.x - mn), p3 = __expf(s23.y - mn);
            float ps = (p0 + p1) + (p2 + p3);
            ps += __shfl_xor_sync(0xffffffffu, ps, 1);
            ps += __shfl_xor_sync(0xffffffffu, ps, 2);
            ps += __shfl_xor_sync(0xffffffffu, ps, 4);
            ps += __shfl_xor_sync(0xffffffffu, ps, 8);
            l_run[i] = l_run[i] * sc + ps;
            m_run[i] = mn;
            unsigned long long scp = frep2(sc);
            fmul2(accp[i][0], scp);
            fmul2(accp[i][1], scp);
            *(float4*)&KP[ty * 8 + i][tx * 4] = make_float4(p0, p1, p2, p3);
        }
        __syncthreads();

        // PV via packed FFMA2
        #pragma unroll 4
        for (int c = 0; c < 64; c++) {
            ulonglong2 bu = *(const ulonglong2*)&Vs[c][tx * 4];
            #pragma unroll
            for (int i = 0; i < 8; i++) {
                unsigned long long pr = frep2(KP[ty * 8 + i][c]);
                ffma2(accp[i][0], pr, bu.x);
                ffma2(accp[i][1], pr, bu.y);
            }
        }
    }

    #pragma unroll
    for (int i = 0; i < 8; i++) {
        float inv = 1.0f / l_run[i];
        float2 a01 = funpack2(accp[i][0]);
        float2 a23 = funpack2(accp[i][1]);
        size_t idx = (rowbase + q0 + ty * 8 + i) * DIM + h * HEAD_DIM + tx * 4;
        bf16 h0, l0, h1, l1;
        split_f(a01.x * inv, h0, l0);
        split_f(a01.y * inv, h1, l1);
        *(__nv_bfloat162*)(ch + idx) = __nv_bfloat162(h0, h1);
        *(__nv_bfloat162*)(cl + idx) = __nv_bfloat162(l0, l1);
        split_f(a23.x * inv, h0, l0);
        split_f(a23.y * inv, h1, l1);
        *(__nv_bfloat162*)(ch + idx + 2) = __nv_bfloat162(h0, h1);
        *(__nv_bfloat162*)(cl + idx + 2) = __nv_bfloat162(l0, l1);
    }
}

// ----------------------------- launch ---------------------------------------
extern "C" void kernel_launch(void* const* d_in, const int* in_sizes, int n_in,
                              void* d_out, int out_size) {
    const float* x      = (const float*)d_in[0];
    const float* ln1_g  = (const float*)d_in[1];
    const float* ln1_b  = (const float*)d_in[2];
    const float* qkv_w  = (const float*)d_in[3];
    const float* qkv_b  = (const float*)d_in[4];
    const float* proj_w = (const float*)d_in[5];
    const float* proj_b = (const float*)d_in[6];
    const float* ln2_g  = (const float*)d_in[7];
    const float* ln2_b  = (const float*)d_in[8];
    const float* fc1_w  = (const float*)d_in[9];
    const float* fc1_b  = (const float*)d_in[10];
    const float* fc2_w  = (const float*)d_in[11];
    const float* fc2_b  = (const float*)d_in[12];
    const float* ln3_g  = (const float*)d_in[13];
    const float* ln3_b  = (const float*)d_in[14];
    float* out = (float*)d_out;

    void *p;
    cudaGetSymbolAddress(&p, g_qkv);  float* qkv  = (float*)p;
    cudaGetSymbolAddress(&p, g_xa);   float* xa   = (float*)p;
    cudaGetSymbolAddress(&p, g_ffin); float* ffin = (float*)p;
    cudaGetSymbolAddress(&p, g_xmlp); float* xmlp = (float*)p;
    cudaGetSymbolAddress(&p, g_bh);   bf16* bh = (bf16*)p;
    cudaGetSymbolAddress(&p, g_bl);   bf16* bl = (bf16*)p;
    cudaGetSymbolAddress(&p, g_ah);   bf16* ah = (bf16*)p;
    cudaGetSymbolAddress(&p, g_al);   bf16* al = (bf16*)p;
    cudaGetSymbolAddress(&p, g_wh);   bf16* wh = (bf16*)p;
    cudaGetSymbolAddress(&p, g_wl);   bf16* wl = (bf16*)p;

    cudaFuncSetAttribute(eb_attn_kernel,
                         cudaFuncAttributeMaxDynamicSharedMemorySize, ATTN_SMEM);
    cudaFuncSetAttribute(eb_mma_gemm<0>,
                         cudaFuncAttributeMaxDynamicSharedMemorySize, MM_SMEM);
    cudaFuncSetAttribute(eb_mma_gemm<1>,
                         cudaFuncAttributeMaxDynamicSharedMemorySize, MM_SMEM);
    cudaFuncSetAttribute(eb_mma_gemm<2>,
                         cudaFuncAttributeMaxDynamicSharedMemorySize, MM_SMEM);

    dim3 wsb(32, 8);

    // 1. LN1 -> split activations (bh/bl)
    eb_ln_kernel<1><<<TOKENS, 256>>>(x, ln1_g, ln1_b, nullptr, bh, bl);
    // 2. QKV
    eb_wsplit_kernel<<<dim3(QKV_N / 32, DIM / 32), wsb>>>(qkv_w, wh, wl, DIM, QKV_N);
    eb_mma_gemm<0><<<dim3(QKV_N / 128, TOKENS / 128), 256, MM_SMEM>>>(
        bh, bl, wh, wl, qkv_b, nullptr, qkv, nullptr, nullptr, DIM, QKV_N);
    // 3. attention -> ctx split (bh/bl)
    eb_attn_kernel<<<dim3(1024 / 64, 16 * HEADS), 128, ATTN_SMEM>>>(qkv, bh, bl);
    // 4. proj + residual(x)
    eb_wsplit_kernel<<<dim3(DIM / 32, DIM / 32), wsb>>>(proj_w, wh, wl, DIM, DIM);
    eb_mma_gemm<1><<<dim3(DIM / 128, TOKENS / 128), 256, MM_SMEM>>>(
        bh, bl, wh, wl, proj_b, x, xa, nullptr, nullptr, DIM, DIM);
    // 5. LN2 -> ffin fp32 + split (bh/bl)
    eb_ln_kernel<2><<<TOKENS, 256>>>(xa, ln2_g, ln2_b, ffin, bh, bl);
    // 6. fc1 + GELU -> hid split (ah/al)
    eb_wsplit_kernel<<<dim3(HIDDEN / 32, DIM / 32), wsb>>>(fc1_w, wh, wl, DIM, HIDDEN);
    eb_mma_gemm<2><<<dim3(HIDDEN / 128, TOKENS / 128), 256, MM_SMEM>>>(
        bh, bl, wh, wl, fc1_b, nullptr, nullptr, ah, al, DIM, HIDDEN);
    // 7. fc2 + residual(ffin)  [reference adds the NORMALIZED tensor]
    eb_wsplit_kernel<<<dim3(DIM / 32, HIDDEN / 32), wsb>>>(fc2_w, wh, wl, HIDDEN, DIM);
    eb_mma_gemm<1><<<dim3(DIM / 128, TOKENS / 128), 256, MM_SMEM>>>(
        ah, al, wh, wl, fc2_b, ffin, xmlp, nullptr, nullptr, HIDDEN, DIM);
    // 8. LN3 -> out
    eb_ln_kernel<0><<<TOKENS, 256>>>(xmlp, ln3_g, ln3_b, out, nullptr, nullptr);
}